// round 7
// baseline (speedup 1.0000x reference)
#include <cuda_runtime.h>
#include <cstdint>

// x: [16, 64, 128, 128] (B, C, H, W), HX = HY = 64.
// Pass 1: 2048 sequences (b,h), T=128 along w.
// Pass 2: 2048 sequences (b,w), T=128 along h.

using ull = unsigned long long;

__device__ float g_pre[2048 * 128 * 64];   // [seq][t][j]
__device__ float g_mid[2048 * 128 * 64];   // [b][w][j][h]
__device__ float g_WTx[64 * 64];           // Wih_x^T: [c][j]
__device__ float g_WTy[64 * 64];
__device__ ull   g_bsdx[64];               // dup'd bias sums
__device__ ull   g_bsdy[64];

__device__ __forceinline__ ull ffma2(ull a, ull b, ull c) {
    ull d;
    asm("fma.rn.f32x2 %0, %1, %2, %3;" : "=l"(d) : "l"(a), "l"(b), "l"(c));
    return d;
}
__device__ __forceinline__ ull addf2(ull a, ull b) {
    ull d;
    asm("add.rn.f32x2 %0, %1, %2;" : "=l"(d) : "l"(a), "l"(b));
    return d;
}
__device__ __forceinline__ ull dup2(float x) {
    unsigned u = __float_as_uint(x);
    return ((ull)u << 32) | (ull)u;
}
__device__ __forceinline__ float lo_f(ull v) { return __uint_as_float((unsigned)(v & 0xffffffffull)); }
__device__ __forceinline__ float hi_f(ull v) { return __uint_as_float((unsigned)(v >> 32)); }
__device__ __forceinline__ float tanh_fast(float x) {
    float r;
    asm("tanh.approx.f32 %0, %1;" : "=f"(r) : "f"(x));
    return r;
}
__device__ __forceinline__ void cp_async16(uint32_t dst, const void* src) {
    asm volatile("cp.async.cg.shared.global [%0], [%1], 16;" :: "r"(dst), "l"(src));
}
#define CP_COMMIT() asm volatile("cp.async.commit_group;")
#define CP_WAIT(n)  asm volatile("cp.async.wait_group %0;" :: "n"(n))

// ---------------------------------------------------------------------------
// Prep: transposed weight tables + dup'd bias sums.
// ---------------------------------------------------------------------------
__global__ void prep_kernel(const float* __restrict__ Wih_x,
                            const float* __restrict__ Wih_y,
                            const float* __restrict__ bih_x,
                            const float* __restrict__ bhh_x,
                            const float* __restrict__ bih_y,
                            const float* __restrict__ bhh_y) {
    int t = threadIdx.x;
    for (int e = t; e < 4096; e += 256) {
        int c = e >> 6, j = e & 63;
        g_WTx[c * 64 + j] = Wih_x[j * 64 + c];
        g_WTy[c * 64 + j] = Wih_y[j * 64 + c];
    }
    if (t < 64) {
        g_bsdx[t] = dup2(bih_x[t] + bhh_x[t]);
        g_bsdy[t] = dup2(bih_y[t] + bhh_y[t]);
    }
}

// ---------------------------------------------------------------------------
// Projection: pre[row][pos][j] = bias[j] + sum_c in[c][pos] * W[j][c]
// Grid 2048 (one block per row, full 128 positions).
// Smem: input tile [c][pos] 32KB + W^T [c][j] 16KB = 48KB.
// Thread tile: 8 positions (4 f32x2 pairs) x 4 outputs -> 16 FFMA2 per c.
// ---------------------------------------------------------------------------
template <int MODE>
__global__ __launch_bounds__(256) void proj_kernel(const float* __restrict__ src) {
    __shared__ float in_sh[64][128];   // [c][pos]  32KB
    __shared__ float W_sh[64][64];     // [c][j]    16KB

    int tid = threadIdx.x;
    int row = blockIdx.x;

    const float* base;
    size_t stride_c;
    if (MODE == 0) {
        int b = row >> 7, h = row & 127;
        base = src + (size_t)b * 1048576 + (size_t)h * 128;
        stride_c = 16384;
    } else {
        base = g_mid + (size_t)row * 8192;
        stride_c = 128;
    }

    uint32_t shW = (uint32_t)__cvta_generic_to_shared(&W_sh[0][0]);
    uint32_t shI = (uint32_t)__cvta_generic_to_shared(&in_sh[0][0]);

    // Stage W^T: 1024 granules (4/thread). Input tile: 2048 granules (8/thread).
    {
        const float* WT = (MODE == 0) ? g_WTx : g_WTy;
        #pragma unroll
        for (int i = 0; i < 4; i++) {
            int e = tid + i * 256;               // 0..1023
            cp_async16(shW + e * 16, WT + e * 4);
        }
        #pragma unroll
        for (int i = 0; i < 8; i++) {
            int e = tid + i * 256;               // 0..2047, 32 granules/row
            int c = e >> 5, g4 = e & 31;
            cp_async16(shI + e * 16, base + (size_t)c * stride_c + g4 * 4);
        }
        CP_COMMIT();
        CP_WAIT(0);
        __syncthreads();
    }

    int pt = tid & 15;    // position group of 8
    int jt = tid >> 4;    // output group of 4

    const ull* bd = ((MODE == 0) ? g_bsdx : g_bsdy) + jt * 4;
    ull a[4][4];          // [pos-pair][output]
    #pragma unroll
    for (int o = 0; o < 4; o++) {
        ull bv = bd[o];
        a[0][o] = bv; a[1][o] = bv; a[2][o] = bv; a[3][o] = bv;
    }

    #pragma unroll 8
    for (int c = 0; c < 64; c++) {
        ulonglong2 X0 = *(const ulonglong2*)&in_sh[c][pt * 8];
        ulonglong2 X1 = *(const ulonglong2*)&in_sh[c][pt * 8 + 4];
        float4 wv = *(const float4*)&W_sh[c][jt * 4];
        ull w0 = dup2(wv.x), w1 = dup2(wv.y), w2 = dup2(wv.z), w3 = dup2(wv.w);
        a[0][0] = ffma2(X0.x, w0, a[0][0]);  a[1][0] = ffma2(X0.y, w0, a[1][0]);
        a[2][0] = ffma2(X1.x, w0, a[2][0]);  a[3][0] = ffma2(X1.y, w0, a[3][0]);
        a[0][1] = ffma2(X0.x, w1, a[0][1]);  a[1][1] = ffma2(X0.y, w1, a[1][1]);
        a[2][1] = ffma2(X1.x, w1, a[2][1]);  a[3][1] = ffma2(X1.y, w1, a[3][1]);
        a[0][2] = ffma2(X0.x, w2, a[0][2]);  a[1][2] = ffma2(X0.y, w2, a[1][2]);
        a[2][2] = ffma2(X1.x, w2, a[2][2]);  a[3][2] = ffma2(X1.y, w2, a[3][2]);
        a[0][3] = ffma2(X0.x, w3, a[0][3]);  a[1][3] = ffma2(X0.y, w3, a[1][3]);
        a[2][3] = ffma2(X1.x, w3, a[2][3]);  a[3][3] = ffma2(X1.y, w3, a[3][3]);
    }

    float* dst = g_pre + (size_t)row * 8192 + (pt * 8) * 64 + jt * 4;
    #pragma unroll
    for (int pp = 0; pp < 4; pp++) {
        float4 o;
        o = make_float4(lo_f(a[pp][0]), lo_f(a[pp][1]), lo_f(a[pp][2]), lo_f(a[pp][3]));
        *(float4*)(dst + (pp * 2 + 0) * 64) = o;
        o = make_float4(hi_f(a[pp][0]), hi_f(a[pp][1]), hi_f(a[pp][2]), hi_f(a[pp][3]));
        *(float4*)(dst + (pp * 2 + 1) * 64) = o;
    }
}

// ---------------------------------------------------------------------------
// Recurrent scan: h_t = tanh(pre_t + Whh @ h_{t-1}); 4 sequences per block,
// 256 threads, pre staged via double-buffered cp.async chunks of 16 steps.
// MODE 0: write g_mid[b][w][j][h];  MODE 1: write out[b][j][h][w].
// Remap store: 16B contiguous groups (4 adjacent positions per j).
// ---------------------------------------------------------------------------
template <int MODE>
__global__ __launch_bounds__(256) void scan_kernel(const float* __restrict__ Whh,
                                                   float* __restrict__ out) {
    __shared__ float pre_sh[2][4][16][64];   // [buf][sl][tt][j] 32KB
    __shared__ float hbuf[2][4][72];         // pad 72: conflict-free remap

    int tid = threadIdx.x;
    int sl  = tid >> 6;
    int j   = tid & 63;
    int s0  = blockIdx.x * 4;
    int b   = s0 >> 7;
    int p0  = s0 & 127;

    const float* preg = g_pre + (size_t)s0 * 8192;

    ull w2[32];
    {
        const ull* wr = (const ull*)(Whh + j * 64);
        #pragma unroll
        for (int i = 0; i < 32; i++) w2[i] = wr[i];
    }

    hbuf[0][sl][j] = 0.f;

    uint32_t preb = (uint32_t)__cvta_generic_to_shared(&pre_sh[0][0][0][0]);

    // chunk 0: 4096 floats = 1024 granules (4/thread)
    {
        #pragma unroll
        for (int i = 0; i < 4; i++) {
            int e = tid + i * 256;
            int seq = e >> 8, off = (e & 255) * 4;
            cp_async16(preb + (seq * 1024 + off) * 4,
                       preg + (size_t)seq * 8192 + off);
        }
        CP_COMMIT();
    }

    int j2 = tid >> 2;        // remap: output channel
    int s2 = tid & 3;         // remap: sequence within block
    float* outp;
    if (MODE == 0) {
        outp = g_mid + (size_t)b * 1048576 + (size_t)j2 * 128 + p0 + s2;   // + t*8192
    } else {
        outp = out + (size_t)b * 1048576 + (size_t)j2 * 16384 + p0 + s2;   // + t*128
    }

    int cur = 0;
    for (int k = 0; k < 8; k++) {
        __syncthreads();                       // buf (k+1)&1 free to overwrite
        if (k < 7) {
            int bk = (k + 1) & 1;
            #pragma unroll
            for (int i = 0; i < 4; i++) {
                int e = tid + i * 256;
                int seq = e >> 8, off = (e & 255) * 4;
                cp_async16(preb + (bk * 4096 + seq * 1024 + off) * 4,
                           preg + (size_t)seq * 8192 + (k + 1) * 1024 + off);
            }
            CP_COMMIT();
            CP_WAIT(1);                        // chunk k landed
        } else {
            CP_WAIT(0);
        }
        __syncthreads();

        const float* pvp = &pre_sh[k & 1][sl][0][j];

        #pragma unroll 4
        for (int tt = 0; tt < 16; tt++) {
            float pv = pvp[tt * 64];

            const ulonglong2* h2 = (const ulonglong2*)hbuf[cur][sl];
            ull a0 = 0, a1 = 0, a2 = 0, a3 = 0;
            #pragma unroll
            for (int i = 0; i < 16; i += 2) {
                ulonglong2 ha = h2[i];
                a0 = ffma2(w2[2 * i],     ha.x, a0);
                a1 = ffma2(w2[2 * i + 1], ha.y, a1);
                ulonglong2 hb = h2[i + 1];
                a2 = ffma2(w2[2 * i + 2], hb.x, a2);
                a3 = ffma2(w2[2 * i + 3], hb.y, a3);
            }
            a0 = addf2(a0, a1);
            a2 = addf2(a2, a3);
            a0 = addf2(a0, a2);
            float s_ = pv + lo_f(a0) + hi_f(a0);
            float hn = tanh_fast(s_);

            int nxt = cur ^ 1;
            hbuf[nxt][sl][j] = hn;
            __syncthreads();

            float v = hbuf[nxt][s2][j2];       // conflict-free remap read
            int t = k * 16 + tt;
            if (MODE == 0) outp[(size_t)t * 8192] = v;
            else           outp[(size_t)t * 128]  = v;

            cur = nxt;
        }
    }
}

// ---------------------------------------------------------------------------
extern "C" void kernel_launch(void* const* d_in, const int* in_sizes, int n_in,
                              void* d_out, int out_size) {
    const float* x     = (const float*)d_in[0];
    const float* Wih_x = (const float*)d_in[1];
    const float* Whh_x = (const float*)d_in[2];
    const float* bih_x = (const float*)d_in[3];
    const float* bhh_x = (const float*)d_in[4];
    const float* Wih_y = (const float*)d_in[5];
    const float* Whh_y = (const float*)d_in[6];
    const float* bih_y = (const float*)d_in[7];
    const float* bhh_y = (const float*)d_in[8];
    float* out = (float*)d_out;

    prep_kernel<<<1, 256>>>(Wih_x, Wih_y, bih_x, bhh_x, bih_y, bhh_y);
    proj_kernel<0><<<2048, 256>>>(x);                 // pre_x
    scan_kernel<0><<<512, 256>>>(Whh_x, nullptr);     // scan w -> g_mid [b][w][j][h]
    proj_kernel<1><<<2048, 256>>>(nullptr);           // pre_y
    scan_kernel<1><<<512, 256>>>(Whh_y, out);         // scan h -> out [b][j][h][w]
}

// round 8
// speedup vs baseline: 1.2662x; 1.2662x over previous
#include <cuda_runtime.h>
#include <cstdint>

// x: [16, 64, 128, 128] (B, C, H, W), HX = HY = 64.
// Pass 1: 2048 sequences (b,h), T=128 along w.
// Pass 2: 2048 sequences (b,w), T=128 along h.

using ull = unsigned long long;

__device__ float g_pre[2048 * 128 * 64];   // [seq][t][j]
__device__ float g_mid[2048 * 128 * 64];   // [b][w][j][h]
__device__ float g_WTx[64 * 64];           // Wih_x^T: [c][j]
__device__ float g_WTy[64 * 64];
__device__ ull   g_bsdx[64];               // dup'd bias sums
__device__ ull   g_bsdy[64];

__device__ __forceinline__ ull ffma2(ull a, ull b, ull c) {
    ull d;
    asm("fma.rn.f32x2 %0, %1, %2, %3;" : "=l"(d) : "l"(a), "l"(b), "l"(c));
    return d;
}
__device__ __forceinline__ ull addf2(ull a, ull b) {
    ull d;
    asm("add.rn.f32x2 %0, %1, %2;" : "=l"(d) : "l"(a), "l"(b));
    return d;
}
__device__ __forceinline__ ull dup2(float x) {
    unsigned u = __float_as_uint(x);
    return ((ull)u << 32) | (ull)u;
}
__device__ __forceinline__ float lo_f(ull v) { return __uint_as_float((unsigned)(v & 0xffffffffull)); }
__device__ __forceinline__ float hi_f(ull v) { return __uint_as_float((unsigned)(v >> 32)); }
__device__ __forceinline__ float tanh_fast(float x) {
    float r;
    asm("tanh.approx.f32 %0, %1;" : "=f"(r) : "f"(x));
    return r;
}
__device__ __forceinline__ void cp_async16(uint32_t dst, const void* src) {
    asm volatile("cp.async.cg.shared.global [%0], [%1], 16;" :: "r"(dst), "l"(src));
}
#define CP_COMMIT() asm volatile("cp.async.commit_group;")
#define CP_WAIT(n)  asm volatile("cp.async.wait_group %0;" :: "n"(n))

// ---------------------------------------------------------------------------
// Prep: transposed weight tables + dup'd bias sums.
// ---------------------------------------------------------------------------
__global__ void prep_kernel(const float* __restrict__ Wih_x,
                            const float* __restrict__ Wih_y,
                            const float* __restrict__ bih_x,
                            const float* __restrict__ bhh_x,
                            const float* __restrict__ bih_y,
                            const float* __restrict__ bhh_y) {
    int t = threadIdx.x;
    for (int e = t; e < 4096; e += 256) {
        int c = e >> 6, j = e & 63;
        g_WTx[c * 64 + j] = Wih_x[j * 64 + c];
        g_WTy[c * 64 + j] = Wih_y[j * 64 + c];
    }
    if (t < 64) {
        g_bsdx[t] = dup2(bih_x[t] + bhh_x[t]);
        g_bsdy[t] = dup2(bih_y[t] + bhh_y[t]);
    }
}

// ---------------------------------------------------------------------------
// Projection: pre[row][pos][j] = bias[j] + sum_c in[c][pos] * W[j][c]
// Grid 2048 (one block per row, full 128 positions).
// Smem: input tile [c][pos] 32KB + W^T [c][j] 16KB = 48KB.
// Mapping: pt = tid>>4 (X reads become warp-broadcast), jt = tid&15
// (W reads 256B conflict-free). 16 FFMA2 per c per thread.
// ---------------------------------------------------------------------------
template <int MODE>
__global__ __launch_bounds__(256) void proj_kernel(const float* __restrict__ src) {
    __shared__ float in_sh[64][128];   // [c][pos]  32KB
    __shared__ float W_sh[64][64];     // [c][j]    16KB

    int tid = threadIdx.x;
    int row = blockIdx.x;

    const float* base;
    size_t stride_c;
    if (MODE == 0) {
        int b = row >> 7, h = row & 127;
        base = src + (size_t)b * 1048576 + (size_t)h * 128;
        stride_c = 16384;
    } else {
        base = g_mid + (size_t)row * 8192;
        stride_c = 128;
    }

    uint32_t shW = (uint32_t)__cvta_generic_to_shared(&W_sh[0][0]);
    uint32_t shI = (uint32_t)__cvta_generic_to_shared(&in_sh[0][0]);

    // Stage W^T: 1024 granules (4/thread). Input tile: 2048 granules (8/thread).
    {
        const float* WT = (MODE == 0) ? g_WTx : g_WTy;
        #pragma unroll
        for (int i = 0; i < 4; i++) {
            int e = tid + i * 256;               // 0..1023
            cp_async16(shW + e * 16, WT + e * 4);
        }
        #pragma unroll
        for (int i = 0; i < 8; i++) {
            int e = tid + i * 256;               // 0..2047, 32 granules/row
            int c = e >> 5, g4 = e & 31;
            cp_async16(shI + e * 16, base + (size_t)c * stride_c + g4 * 4);
        }
        CP_COMMIT();
        CP_WAIT(0);
        __syncthreads();
    }

    int pt = tid >> 4;    // position group of 8 (broadcast X within half-warp)
    int jt = tid & 15;    // output group of 4 (conflict-free W sweep)

    const ull* bd = ((MODE == 0) ? g_bsdx : g_bsdy) + jt * 4;
    ull a[4][4];          // [pos-pair][output]
    #pragma unroll
    for (int o = 0; o < 4; o++) {
        ull bv = bd[o];
        a[0][o] = bv; a[1][o] = bv; a[2][o] = bv; a[3][o] = bv;
    }

    #pragma unroll 8
    for (int c = 0; c < 64; c++) {
        ulonglong2 X0 = *(const ulonglong2*)&in_sh[c][pt * 8];
        ulonglong2 X1 = *(const ulonglong2*)&in_sh[c][pt * 8 + 4];
        float4 wv = *(const float4*)&W_sh[c][jt * 4];
        ull w0 = dup2(wv.x), w1 = dup2(wv.y), w2 = dup2(wv.z), w3 = dup2(wv.w);
        a[0][0] = ffma2(X0.x, w0, a[0][0]);  a[1][0] = ffma2(X0.y, w0, a[1][0]);
        a[2][0] = ffma2(X1.x, w0, a[2][0]);  a[3][0] = ffma2(X1.y, w0, a[3][0]);
        a[0][1] = ffma2(X0.x, w1, a[0][1]);  a[1][1] = ffma2(X0.y, w1, a[1][1]);
        a[2][1] = ffma2(X1.x, w1, a[2][1]);  a[3][1] = ffma2(X1.y, w1, a[3][1]);
        a[0][2] = ffma2(X0.x, w2, a[0][2]);  a[1][2] = ffma2(X0.y, w2, a[1][2]);
        a[2][2] = ffma2(X1.x, w2, a[2][2]);  a[3][2] = ffma2(X1.y, w2, a[3][2]);
        a[0][3] = ffma2(X0.x, w3, a[0][3]);  a[1][3] = ffma2(X0.y, w3, a[1][3]);
        a[2][3] = ffma2(X1.x, w3, a[2][3]);  a[3][3] = ffma2(X1.y, w3, a[3][3]);
    }

    float* dst = g_pre + (size_t)row * 8192 + (pt * 8) * 64 + jt * 4;
    #pragma unroll
    for (int pp = 0; pp < 4; pp++) {
        float4 o;
        o = make_float4(lo_f(a[pp][0]), lo_f(a[pp][1]), lo_f(a[pp][2]), lo_f(a[pp][3]));
        *(float4*)(dst + (pp * 2 + 0) * 64) = o;
        o = make_float4(hi_f(a[pp][0]), hi_f(a[pp][1]), hi_f(a[pp][2]), hi_f(a[pp][3]));
        *(float4*)(dst + (pp * 2 + 1) * 64) = o;
    }
}

// ---------------------------------------------------------------------------
// Recurrent scan: h_t = tanh(pre_t + Whh @ h_{t-1}); 2 sequences per block,
// 128 threads, pre staged via double-buffered cp.async chunks of 16 steps.
// MODE 0: write g_mid[b][w][j][h];  MODE 1: write out[b][j][h][w].
// ---------------------------------------------------------------------------
template <int MODE>
__global__ __launch_bounds__(128, 4) void scan_kernel(const float* __restrict__ Whh,
                                                      float* __restrict__ out) {
    __shared__ float pre_sh[2][2][16][64];   // [buf][sl][tt][j] 16KB
    __shared__ float hbuf[2][2][80];         // pad 80: conflict-free remap

    int tid = threadIdx.x;
    int sl  = tid >> 6;
    int j   = tid & 63;
    int s0  = blockIdx.x * 2;
    int b   = s0 >> 7;
    int p0  = s0 & 127;

    const float* preg = g_pre + (size_t)s0 * 8192;

    ull w2[32];
    {
        const ull* wr = (const ull*)(Whh + j * 64);
        #pragma unroll
        for (int i = 0; i < 32; i++) w2[i] = wr[i];
    }

    hbuf[0][sl][j] = 0.f;

    uint32_t preb = (uint32_t)__cvta_generic_to_shared(&pre_sh[0][0][0][0]);

    // chunk 0: 2048 floats (2 seqs x 16 steps x 64)
    {
        #pragma unroll
        for (int i = 0; i < 4; i++) {
            int e = tid * 4 + i * 512;
            int seq = e >> 10, off = e & 1023;
            cp_async16(preb + e * 4, preg + (size_t)seq * 8192 + off);
        }
        CP_COMMIT();
    }

    int j2 = tid >> 1;        // remap: output channel
    int s2 = tid & 1;         // remap: sequence within block
    float* outp;
    if (MODE == 0) {
        outp = g_mid + (size_t)b * 1048576 + (size_t)j2 * 128 + p0 + s2;   // + t*8192
    } else {
        outp = out + (size_t)b * 1048576 + (size_t)j2 * 16384 + p0 + s2;   // + t*128
    }

    int cur = 0;
    for (int k = 0; k < 8; k++) {
        __syncthreads();                       // buf (k+1)&1 free to overwrite
        if (k < 7) {
            int bk = (k + 1) & 1;
            #pragma unroll
            for (int i = 0; i < 4; i++) {
                int e = tid * 4 + i * 512;
                int seq = e >> 10, off = e & 1023;
                cp_async16(preb + (bk * 2048 + e) * 4,
                           preg + (size_t)seq * 8192 + (k + 1) * 1024 + off);
            }
            CP_COMMIT();
            CP_WAIT(1);                        // chunk k landed
        } else {
            CP_WAIT(0);
        }
        __syncthreads();

        const float* pvp = &pre_sh[k & 1][sl][0][j];

        #pragma unroll 4
        for (int tt = 0; tt < 16; tt++) {
            float pv = pvp[tt * 64];

            const ulonglong2* h2 = (const ulonglong2*)hbuf[cur][sl];
            ull a0 = 0, a1 = 0, a2 = 0, a3 = 0;
            #pragma unroll
            for (int i = 0; i < 16; i += 2) {
                ulonglong2 ha = h2[i];
                a0 = ffma2(w2[2 * i],     ha.x, a0);
                a1 = ffma2(w2[2 * i + 1], ha.y, a1);
                ulonglong2 hb = h2[i + 1];
                a2 = ffma2(w2[2 * i + 2], hb.x, a2);
                a3 = ffma2(w2[2 * i + 3], hb.y, a3);
            }
            a0 = addf2(a0, a1);
            a2 = addf2(a2, a3);
            a0 = addf2(a0, a2);
            float s_ = pv + lo_f(a0) + hi_f(a0);
            float hn = tanh_fast(s_);

            int nxt = cur ^ 1;
            hbuf[nxt][sl][j] = hn;
            __syncthreads();

            float v = hbuf[nxt][s2][j2];       // conflict-free remap read
            int t = k * 16 + tt;
            if (MODE == 0) outp[(size_t)t * 8192] = v;
            else           outp[(size_t)t * 128]  = v;

            cur = nxt;
        }
    }
}

// ---------------------------------------------------------------------------
extern "C" void kernel_launch(void* const* d_in, const int* in_sizes, int n_in,
                              void* d_out, int out_size) {
    const float* x     = (const float*)d_in[0];
    const float* Wih_x = (const float*)d_in[1];
    const float* Whh_x = (const float*)d_in[2];
    const float* bih_x = (const float*)d_in[3];
    const float* bhh_x = (const float*)d_in[4];
    const float* Wih_y = (const float*)d_in[5];
    const float* Whh_y = (const float*)d_in[6];
    const float* bih_y = (const float*)d_in[7];
    const float* bhh_y = (const float*)d_in[8];
    float* out = (float*)d_out;

    prep_kernel<<<1, 256>>>(Wih_x, Wih_y, bih_x, bhh_x, bih_y, bhh_y);
    proj_kernel<0><<<2048, 256>>>(x);                  // pre_x
    scan_kernel<0><<<1024, 128>>>(Whh_x, nullptr);     // scan w -> g_mid [b][w][j][h]
    proj_kernel<1><<<2048, 256>>>(nullptr);            // pre_y
    scan_kernel<1><<<1024, 128>>>(Whh_y, out);         // scan h -> out [b][j][h][w]
}